// round 15
// baseline (speedup 1.0000x reference)
#include <cuda_runtime.h>
#include <cstdint>

#define NB 2048
#define NF 64
#define NR 32
#define NP 16
#define NC 128

// ---------------- scratch ----------------
__device__ float g_wch [NB*1024];
__device__ float g_vch [NB*1024];
__device__ float g_vep0[NB*1024];
__device__ float g_vep2[NB*1024];
__device__ float g_Wk  [3*NB*1024];
__device__ float g_small[NB*264];
// pre-split tf32 hi/lo buffers
__device__ float g_ctxh[NB*NC];
__device__ float g_ctxl[NB*NC];
__device__ float g_Bh  [8*128*1024];
__device__ float g_Bl  [8*128*1024];

__device__ __forceinline__ float sigmoidf_(float x) { return 1.f/(1.f + __expf(-x)); }

// ---- 3xTF32 helpers (family-portable PTX, sm_80+) ----
__device__ __forceinline__ void tf32split_(float x, uint32_t& hi, uint32_t& lo) {
    uint32_t h;
    asm("cvt.rna.tf32.f32 %0, %1;" : "=r"(h) : "f"(x));
    float r = x - __uint_as_float(h);
    uint32_t l;
    asm("cvt.rna.tf32.f32 %0, %1;" : "=r"(l) : "f"(r));
    hi = h; lo = l;
}
__device__ __forceinline__ void mma_tf32_(float* c, const uint32_t* a, uint32_t b0, uint32_t b1) {
    asm volatile(
        "mma.sync.aligned.m16n8k8.row.col.f32.tf32.tf32.f32 "
        "{%0,%1,%2,%3}, {%4,%5,%6,%7}, {%8,%9}, {%0,%1,%2,%3};"
        : "+f"(c[0]), "+f"(c[1]), "+f"(c[2]), "+f"(c[3])
        : "r"(a[0]), "r"(a[1]), "r"(a[2]), "r"(a[3]), "r"(b0), "r"(b1));
}

// ---- small-projection column map (258 cols) ----
__device__ __forceinline__ const float* sp_col(int n, int& stride,
    const float* mod_W, const float* wdl_W, const float* wep_W,
    const float* wnc_W, const float* mb_W, const float* wnd_W, const float* wne_W)
{
    if (n < 96)  { stride = 96; return mod_W + n; }
    if (n < 112) { stride = 16; return wdl_W + (n-96); }
    if (n < 128) { stride = 64; return wep_W + (n-112)*4; }
    if (n < 144) { stride = 64; return wep_W + (n-128)*4 + 2; }
    if (n < 208) { stride = 64; return wnc_W + (n-144); }
    if (n < 256) { int idx = n-208; stride = 16; return mb_W + (idx>>4)*2048 + (idx&15); }
    if (n == 256){ stride = 1; return wnd_W; }
    stride = 1; return wne_W;
}
__device__ __forceinline__ float sp_bias(int n,
    const float* mod_b, const float* wdl_b, const float* wep_b,
    const float* wnc_b, const float* mb_b, const float* wnd_b, const float* wne_b)
{
    if (n < 96)  return mod_b[n];
    if (n < 112) return wdl_b[n-96];
    if (n < 128) return wep_b[(n-112)*4];
    if (n < 144) return wep_b[(n-128)*4 + 2];
    if (n < 208) return wnc_b[n-144];
    if (n < 256) return mb_b[n-208];
    if (n == 256) return wnd_b[0];
    return wne_b[0];
}

// =====================================================================
// Kernel 0: pre-split ctx and all B slices into tf32 hi/lo buffers.
// grid = 1024 (ctx) + 4096 (weights) CTAs of 256.
// =====================================================================
__global__ __launch_bounds__(256) void prep_split(
    const float* __restrict__ ctx,
    const float* __restrict__ wch_W, const float* __restrict__ vch_W,
    const float* __restrict__ vep_W, const float* __restrict__ m_W,
    const float* __restrict__ mod_W, const float* __restrict__ wdl_W,
    const float* __restrict__ wep_W, const float* __restrict__ wnc_W,
    const float* __restrict__ mb_W,  const float* __restrict__ wnd_W,
    const float* __restrict__ wne_W)
{
    int gid = blockIdx.x*256 + threadIdx.x;
    if (blockIdx.x < 1024) {
        float v = ctx[gid];
        uint32_t h, l; tf32split_(v, h, l);
        g_ctxh[gid] = __uint_as_float(h);
        g_ctxl[gid] = __uint_as_float(l);
    } else {
        int i = gid - 262144;           // 0..1048575
        int z = i >> 17, rem = i & 131071;
        int k = rem >> 10, n = rem & 1023;
        float v = 0.f;
        switch (z) {
            case 0: v = wch_W[k*1024 + n]; break;
            case 1: v = vch_W[k*1024 + n]; break;
            case 2: v = vep_W[k*4096 + n*4]; break;
            case 3: v = vep_W[k*4096 + n*4 + 2]; break;
            case 4: case 5: case 6: v = m_W[(z-4)*131072 + k*1024 + n]; break;
            default:
                if (n < 258) {
                    int s;
                    const float* p = sp_col(n, s, mod_W, wdl_W, wep_W, wnc_W, mb_W, wnd_W, wne_W);
                    v = p[k*s];
                }
                break;
        }
        uint32_t h, l; tf32split_(v, h, l);
        g_Bh[i] = __uint_as_float(h);
        g_Bl[i] = __uint_as_float(l);
    }
}

// smem layout (floats): A stride 36, B stride 136.
#define PA 36
#define PB 136
#define OFF_AHI 0
#define OFF_ALO (128*PA)
#define OFF_BHI (2*128*PA)
#define OFF_BLO (2*128*PA + 32*PB)
#define OFF_BIAS (2*128*PA + 2*32*PB)
#define SM_FLOATS (OFF_BIAS + 128)
#define SM_BYTES  (SM_FLOATS*4)

// =====================================================================
// Kernel 1: 8 GEMM slices (7 big + small gather), 3xTF32 mma.sync.
// Loader = pure float4 copies of pre-split data. 944 packed CTAs.
// =====================================================================
__global__ __launch_bounds__(256, 3) void proj_tc(
    const float* __restrict__ wch_b, const float* __restrict__ vch_b,
    const float* __restrict__ vep_b, const float* __restrict__ m_Wb,
    const float* __restrict__ mod_b, const float* __restrict__ wdl_b,
    const float* __restrict__ wep_b, const float* __restrict__ wnc_b,
    const float* __restrict__ mb_b,  const float* __restrict__ wnd_b,
    const float* __restrict__ wne_b)
{
    const int bid = blockIdx.x;
    int bz, bx, by;
    if (bid < 896) { bz = bid >> 7; int rem = bid & 127; bx = rem >> 4; by = rem & 15; }
    else           { bz = 7; int rem = bid - 896; bx = rem >> 4; by = rem & 15; }

    const float* bias = nullptr; float* outp;
    int nstride = 1, noff = 0, ld_out = 1024, small = 0;
    switch (bz) {
        case 0: bias = wch_b; outp = g_wch; break;
        case 1: bias = vch_b; outp = g_vch; break;
        case 2: bias = vep_b; outp = g_vep0; nstride = 4; noff = 0; break;
        case 3: bias = vep_b; outp = g_vep2; nstride = 4; noff = 2; break;
        case 7: small = 1; outp = g_small; ld_out = 264; break;
        default: bias = m_Wb + (bz-4)*1024; outp = g_Wk + (bz-4)*NB*1024; break;
    }

    const int n0 = bx * 128;
    const int m0 = by * 128;

    extern __shared__ __align__(16) float smem[];
    float* AhF = smem + OFF_AHI;
    float* AlF = smem + OFF_ALO;
    float* BhF = smem + OFF_BHI;
    float* BlF = smem + OFF_BLO;
    float* bias_s = smem + OFF_BIAS;
    const uint32_t* Ah = reinterpret_cast<const uint32_t*>(AhF);
    const uint32_t* Al = reinterpret_cast<const uint32_t*>(AlF);
    const uint32_t* Bh = reinterpret_cast<const uint32_t*>(BhF);
    const uint32_t* Bl = reinterpret_cast<const uint32_t*>(BlF);

    const int tid  = threadIdx.x;
    const int wid  = tid >> 5, lane = tid & 31;
    const int g    = lane >> 2, tq = lane & 3;
    const int wm   = wid >> 1, wn = wid & 1;

    if (tid < 128) {
        float bv;
        if (small) bv = (n0 + tid < 258) ? sp_bias(n0+tid, mod_b, wdl_b, wep_b, wnc_b, mb_b, wnd_b, wne_b) : 0.f;
        else       bv = bias[(n0+tid)*nstride + noff];
        bias_s[tid] = bv;
    }

    const float* gBh = g_Bh + (size_t)bz*131072;
    const float* gBl = g_Bl + (size_t)bz*131072;

    float c[2][8][4];
    #pragma unroll
    for (int mi = 0; mi < 2; mi++)
        #pragma unroll
        for (int ni = 0; ni < 8; ni++)
            #pragma unroll
            for (int q = 0; q < 4; q++) c[mi][ni][q] = 0.f;

    for (int chunk = 0; chunk < 4; chunk++) {
        const int kc = chunk*32;
        if (chunk) __syncthreads();

        // A tile: 128 m x 32 k, float4 copies of pre-split ctx
        #pragma unroll
        for (int it = 0; it < 4; it++) {
            int idx = tid + it*256;            // 0..1023
            int m = idx >> 3, q4 = (idx & 7)*4;
            *(float4*)&AhF[m*PA + q4] = *(const float4*)&g_ctxh[(m0+m)*NC + kc + q4];
            *(float4*)&AlF[m*PA + q4] = *(const float4*)&g_ctxl[(m0+m)*NC + kc + q4];
        }
        // B tile: 32 k x 128 n
        #pragma unroll
        for (int it = 0; it < 4; it++) {
            int idx = tid + it*256;
            int k = idx >> 5, q4 = (idx & 31)*4;
            *(float4*)&BhF[k*PB + q4] = *(const float4*)&gBh[(kc+k)*1024 + n0 + q4];
            *(float4*)&BlF[k*PB + q4] = *(const float4*)&gBl[(kc+k)*1024 + n0 + q4];
        }
        __syncthreads();

        #pragma unroll
        for (int term = 0; term < 3; term++) {
            const uint32_t* As = (term == 2) ? Al : Ah;
            const uint32_t* Bs = (term == 1) ? Bl : Bh;
            #pragma unroll
            for (int kb = 0; kb < 32; kb += 8) {
                uint32_t a[2][4];
                #pragma unroll
                for (int mi = 0; mi < 2; mi++) {
                    int r0 = wm*32 + mi*16 + g;
                    a[mi][0] = As[(r0    )*PA + kb + tq];
                    a[mi][1] = As[(r0 + 8)*PA + kb + tq];
                    a[mi][2] = As[(r0    )*PA + kb + tq + 4];
                    a[mi][3] = As[(r0 + 8)*PA + kb + tq + 4];
                }
                #pragma unroll
                for (int ni = 0; ni < 8; ni++) {
                    int nb = wn*64 + ni*8 + g;
                    uint32_t b0 = Bs[(kb + tq    )*PB + nb];
                    uint32_t b1 = Bs[(kb + tq + 4)*PB + nb];
                    mma_tf32_(c[0][ni], a[0], b0, b1);
                    mma_tf32_(c[1][ni], a[1], b0, b1);
                }
            }
        }
    }
    __syncthreads();

    // ---- epilogue: stage warp tile 32x65, coalesced out ----
    float* stage = smem + wid*(32*65);
    #pragma unroll
    for (int mi = 0; mi < 2; mi++)
        #pragma unroll
        for (int ni = 0; ni < 8; ni++) {
            int r0 = mi*16 + g;
            int cc = ni*8 + 2*tq;
            stage[(r0    )*65 + cc    ] = c[mi][ni][0];
            stage[(r0    )*65 + cc + 1] = c[mi][ni][1];
            stage[(r0 + 8)*65 + cc    ] = c[mi][ni][2];
            stage[(r0 + 8)*65 + cc + 1] = c[mi][ni][3];
        }
    __syncwarp();
    const int ncol = wn*64;
    const int cg0 = n0 + ncol + lane;
    const int cg1 = cg0 + 32;
    #pragma unroll 4
    for (int r = 0; r < 32; r++) {
        int m = m0 + wm*32 + r;
        float v0 = stage[r*65 + lane]      + bias_s[ncol + lane];
        float v1 = stage[r*65 + 32 + lane] + bias_s[ncol + 32 + lane];
        if (!small || cg0 < 258) outp[(size_t)m*ld_out + cg0] = v0;
        if (!small || cg1 < 258) outp[(size_t)m*ld_out + cg1] = v1;
    }
}

// =====================================================================
// Kernel 2: per-batch fused kernel (unchanged from R14, 139.4us).
// =====================================================================
__global__ __launch_bounds__(256, 4) void scan_kernel(
    const float* __restrict__ form, float* __restrict__ out)
{
    const int b    = blockIdx.x;
    const int tid  = threadIdx.x;
    const int lane = tid & 31, wid = tid >> 5;

    __shared__ __align__(16) float form_t[32][68];
    __shared__ __align__(16) float big[3072];
    __shared__ float match_s[32][16];
    __shared__ float cw_s[96*32];
    __shared__ float segp_s[256];
    __shared__ __align__(16) float sym_s[32][64];
    __shared__ float sm_s[264];
    __shared__ float wnc_s[64];
    __shared__ float mod0_s[16], wdl_s[16], wep0_s[16], wep2_s[16];
    __shared__ float g_s[96], posn_s[96];
    __shared__ float scal2[2];

    for (int i = tid; i < 2048; i += 256) form_t[i & 31][i >> 5] = form[b*2048 + i];
    for (int j = tid; j < 258; j += 256) sm_s[j] = g_small[b*264 + j];
    for (int i = tid; i < 3072; i += 256)
        big[i] = g_Wk[(i >> 10)*(NB*1024) + b*1024 + (i & 1023)];
    __syncthreads();

    if (tid < 16) {
        float m[6], mx = -1e30f;
        #pragma unroll
        for (int ch = 0; ch < 6; ch++) { m[ch] = sm_s[tid*6+ch]; mx = fmaxf(mx, m[ch]); }
        float s = 0.f;
        #pragma unroll
        for (int ch = 0; ch < 6; ch++) { m[ch] = __expf(m[ch]-mx); s += m[ch]; }
        float inv = 1.f/s;
        mod0_s[tid] = m[0]*inv;
        wdl_s[tid]  = m[1]*inv*sm_s[96+tid];
        wep0_s[tid] = m[2]*inv*sm_s[112+tid];
        wep2_s[tid] = m[4]*inv*sm_s[128+tid];
    } else if (tid >= 64 && tid < 128) {
        wnc_s[tid-64] = __expf(sm_s[144 + tid-64]);
    } else if (tid == 128) scal2[0] = __expf(sm_s[256]);
    else if (tid == 129)   scal2[1] = __expf(sm_s[257]);

    {
        const int p0 = wid, p1 = wid + 8, r = lane;
        float prod0 = 1.f, prod1 = 1.f;
        #pragma unroll
        for (int k = 0; k < 3; k++) {
            float sa = sm_s[208 + k*16 + p0];
            float sb = sm_s[208 + k*16 + p1];
            int rr = r + k - 1;
            if (rr >= 0 && rr < 32) {
                const float* w0p = &big[k*1024 + p0*64];
                const float* w1p = &big[k*1024 + p1*64];
                float sa2 = 0.f, sb2 = 0.f;
                #pragma unroll 8
                for (int f = 0; f < 64; f += 8) {
                    float4 fv = *(const float4*)&form_t[rr][f];
                    float4 w0 = *(const float4*)&w0p[f];
                    float4 w1 = *(const float4*)&w1p[f];
                    sa  += w0.x*fv.x + w0.y*fv.y + w0.z*fv.z + w0.w*fv.w;
                    sb  += w1.x*fv.x + w1.y*fv.y + w1.z*fv.z + w1.w*fv.w;
                    float4 fv2 = *(const float4*)&form_t[rr][f+4];
                    float4 w02 = *(const float4*)&w0p[f+4];
                    float4 w12 = *(const float4*)&w1p[f+4];
                    sa2 += w02.x*fv2.x + w02.y*fv2.y + w02.z*fv2.z + w02.w*fv2.w;
                    sb2 += w12.x*fv2.x + w12.y*fv2.y + w12.z*fv2.z + w12.w*fv2.w;
                }
                sa += sa2; sb += sb2;
            }
            prod0 *= sigmoidf_(sa);
            prod1 *= sigmoidf_(sb);
        }
        match_s[r][p0] = prod0;
        match_s[r][p1] = prod1;
    }
    __syncthreads();

    {
        const float* pwch = g_wch + b*1024;
        const float* pvch = g_vch + b*1024;
        for (int i = tid; i < 1024; i += 256) {
            float u1 = mod0_s[i >> 6]*pwch[i];
            big[i]        = u1;
            big[1024 + i] = fmaxf(u1, 0.f)*pvch[i];
        }
    }
    if (tid < 96) {
        int i = tid/3, ph = tid - 3*i;
        const float* wv = (ph == 0) ? wep0_s : (ph == 1 ? wdl_s : wep2_s);
        float s = 0.f;
        #pragma unroll
        for (int p = 0; p < 16; p++) s += match_s[i][p]*wv[p];
        g_s[tid] = (ph == 1) ? (1.f - sigmoidf_(s - scal2[0]))
                             : sigmoidf_(s - scal2[1]);
    }
    __syncthreads();

    if (wid == 0) {
        float a0 = g_s[lane*3+0], a1 = g_s[lane*3+1], a2 = g_s[lane*3+2];
        float loc = a0 + a1 + a2;
        float sc = loc;
        #pragma unroll
        for (int off = 1; off < 32; off <<= 1) {
            float v = __shfl_up_sync(0xffffffffu, sc, off);
            if (lane >= off) sc += v;
        }
        float excl = sc - loc;
        posn_s[lane*3+0] = excl;
        posn_s[lane*3+1] = excl + a0;
        posn_s[lane*3+2] = excl + a0 + a1;
    }
    __syncthreads();

    #pragma unroll 4
    for (int k2 = 0; k2 < 12; k2++) {
        int st = wid*12 + k2;
        float pp = posn_s[st];
        float d  = pp - (float)lane;
        float rstar = fminf(fmaxf(rintf(pp), 0.f), 31.f);
        float dm = pp - rstar;
        float mx = -2.f*dm*dm;
        float e  = __expf(-2.f*d*d - mx);
        float ssum = e;
        #pragma unroll
        for (int off = 16; off; off >>= 1) ssum += __shfl_xor_sync(0xffffffffu, ssum, off);
        cw_s[st*32 + lane] = g_s[st]*e/ssum;
    }
    __syncthreads();

    {
        int st0 = wid*12;
        float run = 1.f;
        #pragma unroll
        for (int k2 = 11; k2 >= 0; k2--) {
            float cc = cw_s[(st0+k2)*32 + lane];
            cw_s[(st0+k2)*32 + lane] = cc*run;
            run *= (1.f - cc);
        }
        segp_s[wid*32 + lane] = run;
    }
    __syncthreads();
    {
        float mult = 1.f;
        #pragma unroll
        for (int w2 = 7; w2 >= 1; w2--) {
            float sp = segp_s[w2*32 + lane];
            if (w2 > wid) mult *= sp;
        }
        if (mult != 1.f) {
            int st0 = wid*12;
            #pragma unroll
            for (int k2 = 0; k2 < 12; k2++)
                cw_s[(st0+k2)*32 + lane] *= mult;
        }
    }
    __syncthreads();

    {
        int f4 = tid & 15, ii = tid >> 4;
        int f = f4*4;
        for (int rep = 0; rep < 2; rep++) {
            int i = ii + rep*16;
            float4 s1 = {0,0,0,0}, s2 = {0,0,0,0};
            #pragma unroll 8
            for (int p = 0; p < 16; p++) {
                float m = match_s[i][p];
                float4 u1 = *(const float4*)&big[p*64 + f];
                float4 u2 = *(const float4*)&big[1024 + p*64 + f];
                s1.x += m*u1.x; s1.y += m*u1.y; s1.z += m*u1.z; s1.w += m*u1.w;
                s2.x += m*u2.x; s2.y += m*u2.y; s2.z += m*u2.z; s2.w += m*u2.w;
            }
            float4 sy = *(const float4*)&form_t[i][f];
            float4 v;
            v.x = sy.x + sigmoidf_(s1.x - wnc_s[f  ])*(s2.x - sy.x);
            v.y = sy.y + sigmoidf_(s1.y - wnc_s[f+1])*(s2.y - sy.y);
            v.z = sy.z + sigmoidf_(s1.z - wnc_s[f+2])*(s2.z - sy.z);
            v.w = sy.w + sigmoidf_(s1.w - wnc_s[f+3])*(s2.w - sy.w);
            *(float4*)&sym_s[i][f] = v;
        }
    }
    __syncthreads();

    float2* Mpair = reinterpret_cast<float2*>(&form_t[0][0]);
    {
        const float* pv0 = g_vep0 + b*1024;
        const float* pv2 = g_vep2 + b*1024;
        for (int i = tid; i < 1024; i += 256) {
            int p = i >> 6;
            big[i]        = fmaxf(wep0_s[p], 0.f)*pv0[i];
            big[1024 + i] = fmaxf(wep2_s[p], 0.f)*pv2[i];
        }
    }
    {
        int p0 = wid, p1 = wid + 8;
        float a00 = 0.f, a01 = 0.f, a20 = 0.f, a21 = 0.f;
        #pragma unroll 8
        for (int i = 0; i < 32; i++) {
            float w0 = cw_s[(3*i  )*32 + lane];
            float w2 = cw_s[(3*i+2)*32 + lane];
            float m0 = match_s[i][p0], m1v = match_s[i][p1];
            a00 += m0*w0;  a01 += m1v*w0;
            a20 += m0*w2;  a21 += m1v*w2;
        }
        Mpair[p0*32 + lane] = make_float2(a00, a20);
        Mpair[p1*32 + lane] = make_float2(a01, a21);
    }
    __syncthreads();

    const int fb = wid*8;
    {
        float o0=0.f,o1=0.f,o2=0.f,o3=0.f,o4=0.f,o5=0.f,o6=0.f,o7=0.f;
        #pragma unroll 8
        for (int p = 0; p < 16; p++) {
            float2 ap = Mpair[p*32 + lane];
            float a0 = ap.x, a2 = ap.y;
            float4 v00 = *(const float4*)&big[p*64 + fb];
            float4 v01 = *(const float4*)&big[p*64 + fb + 4];
            float4 v20 = *(const float4*)&big[1024 + p*64 + fb];
            float4 v21 = *(const float4*)&big[1024 + p*64 + fb + 4];
            o0 += a0*v00.x + a2*v20.x;  o1 += a0*v00.y + a2*v20.y;
            o2 += a0*v00.z + a2*v20.z;  o3 += a0*v00.w + a2*v20.w;
            o4 += a0*v01.x + a2*v21.x;  o5 += a0*v01.y + a2*v21.y;
            o6 += a0*v01.z + a2*v21.z;  o7 += a0*v01.w + a2*v21.w;
        }
        #pragma unroll 8
        for (int i = 0; i < 32; i++) {
            float w1 = cw_s[(3*i+1)*32 + lane];
            float4 s0 = *(const float4*)&sym_s[i][fb];
            float4 s1v = *(const float4*)&sym_s[i][fb + 4];
            o0 += w1*s0.x;  o1 += w1*s0.y;  o2 += w1*s0.z;  o3 += w1*s0.w;
            o4 += w1*s1v.x; o5 += w1*s1v.y; o6 += w1*s1v.z; o7 += w1*s1v.w;
        }
        out[b*2048 + (fb  )*32 + lane] = o0;
        out[b*2048 + (fb+1)*32 + lane] = o1;
        out[b*2048 + (fb+2)*32 + lane] = o2;
        out[b*2048 + (fb+3)*32 + lane] = o3;
        out[b*2048 + (fb+4)*32 + lane] = o4;
        out[b*2048 + (fb+5)*32 + lane] = o5;
        out[b*2048 + (fb+6)*32 + lane] = o6;
        out[b*2048 + (fb+7)*32 + lane] = o7;
    }
}

// =====================================================================
extern "C" void kernel_launch(void* const* d_in, const int* in_sizes, int n_in,
                              void* d_out, int out_size)
{
    (void)in_sizes; (void)n_in; (void)out_size;
    const float* form  = (const float*)d_in[0];
    const float* ctx   = (const float*)d_in[1];
    const float* mod_W = (const float*)d_in[2];
    const float* mod_b = (const float*)d_in[3];
    const float* wch_W = (const float*)d_in[4];
    const float* wch_b = (const float*)d_in[5];
    const float* wdl_W = (const float*)d_in[6];
    const float* wdl_b = (const float*)d_in[7];
    const float* wep_W = (const float*)d_in[8];
    const float* wep_b = (const float*)d_in[9];
    const float* vch_W = (const float*)d_in[10];
    const float* vch_b = (const float*)d_in[11];
    const float* vep_W = (const float*)d_in[12];
    const float* vep_b = (const float*)d_in[13];
    const float* wnc_W = (const float*)d_in[14];
    const float* wnc_b = (const float*)d_in[15];
    const float* wnd_W = (const float*)d_in[16];
    const float* wnd_b = (const float*)d_in[17];
    const float* wne_W = (const float*)d_in[18];
    const float* wne_b = (const float*)d_in[19];
    const float* m_W   = (const float*)d_in[20];
    const float* m_Wb  = (const float*)d_in[21];
    const float* mb_W  = (const float*)d_in[22];
    const float* mb_b  = (const float*)d_in[23];

    static int smem_set = 0;
    if (!smem_set) {
        cudaFuncSetAttribute(proj_tc, cudaFuncAttributeMaxDynamicSharedMemorySize, SM_BYTES);
        smem_set = 1;
    }

    prep_split<<<5120, 256>>>(ctx, wch_W, vch_W, vep_W, m_W,
                              mod_W, wdl_W, wep_W, wnc_W, mb_W, wnd_W, wne_W);

    proj_tc<<<944, 256, SM_BYTES>>>(wch_b, vch_b, vep_b, m_Wb,
                                    mod_b, wdl_b, wep_b, wnc_b, mb_b, wnd_b, wne_b);

    scan_kernel<<<NB, 256>>>(form, (float*)d_out);
}

// round 16
// speedup vs baseline: 1.4889x; 1.4889x over previous
#include <cuda_runtime.h>
#include <cstdint>

#define NB 2048
#define NF 64
#define NR 32
#define NP 16
#define NC 128

// ---------------- scratch ----------------
__device__ float g_wch [NB*1024];
__device__ float g_vch [NB*1024];
__device__ float g_vep0[NB*1024];
__device__ float g_vep2[NB*1024];
__device__ float g_Wk  [3*NB*1024];
__device__ float g_small[NB*264];
// pre-split tf32 hi/lo buffers
__device__ float g_ctxh[NB*NC];
__device__ float g_ctxl[NB*NC];
__device__ float g_Bh  [8*128*1024];
__device__ float g_Bl  [8*128*1024];

__device__ __forceinline__ float sigmoidf_(float x) { return 1.f/(1.f + __expf(-x)); }

// ---- 3xTF32 helpers (family-portable PTX, sm_80+) ----
__device__ __forceinline__ void tf32split_(float x, uint32_t& hi, uint32_t& lo) {
    uint32_t h;
    asm("cvt.rna.tf32.f32 %0, %1;" : "=r"(h) : "f"(x));
    float r = x - __uint_as_float(h);
    uint32_t l;
    asm("cvt.rna.tf32.f32 %0, %1;" : "=r"(l) : "f"(r));
    hi = h; lo = l;
}
__device__ __forceinline__ void mma_tf32_(float* c, const uint32_t* a, uint32_t b0, uint32_t b1) {
    asm volatile(
        "mma.sync.aligned.m16n8k8.row.col.f32.tf32.tf32.f32 "
        "{%0,%1,%2,%3}, {%4,%5,%6,%7}, {%8,%9}, {%0,%1,%2,%3};"
        : "+f"(c[0]), "+f"(c[1]), "+f"(c[2]), "+f"(c[3])
        : "r"(a[0]), "r"(a[1]), "r"(a[2]), "r"(a[3]), "r"(b0), "r"(b1));
}

// ---- small-projection column map (258 cols) ----
__device__ __forceinline__ const float* sp_col(int n, int& stride,
    const float* mod_W, const float* wdl_W, const float* wep_W,
    const float* wnc_W, const float* mb_W, const float* wnd_W, const float* wne_W)
{
    if (n < 96)  { stride = 96; return mod_W + n; }
    if (n < 112) { stride = 16; return wdl_W + (n-96); }
    if (n < 128) { stride = 64; return wep_W + (n-112)*4; }
    if (n < 144) { stride = 64; return wep_W + (n-128)*4 + 2; }
    if (n < 208) { stride = 64; return wnc_W + (n-144); }
    if (n < 256) { int idx = n-208; stride = 16; return mb_W + (idx>>4)*2048 + (idx&15); }
    if (n == 256){ stride = 1; return wnd_W; }
    stride = 1; return wne_W;
}
__device__ __forceinline__ float sp_bias(int n,
    const float* mod_b, const float* wdl_b, const float* wep_b,
    const float* wnc_b, const float* mb_b, const float* wnd_b, const float* wne_b)
{
    if (n < 96)  return mod_b[n];
    if (n < 112) return wdl_b[n-96];
    if (n < 128) return wep_b[(n-112)*4];
    if (n < 144) return wep_b[(n-128)*4 + 2];
    if (n < 208) return wnc_b[n-144];
    if (n < 256) return mb_b[n-208];
    if (n == 256) return wnd_b[0];
    return wne_b[0];
}

// =====================================================================
// Kernel 0: pre-split ctx and all B slices into tf32 hi/lo buffers.
// =====================================================================
__global__ __launch_bounds__(256) void prep_split(
    const float* __restrict__ ctx,
    const float* __restrict__ wch_W, const float* __restrict__ vch_W,
    const float* __restrict__ vep_W, const float* __restrict__ m_W,
    const float* __restrict__ mod_W, const float* __restrict__ wdl_W,
    const float* __restrict__ wep_W, const float* __restrict__ wnc_W,
    const float* __restrict__ mb_W,  const float* __restrict__ wnd_W,
    const float* __restrict__ wne_W)
{
    int gid = blockIdx.x*256 + threadIdx.x;
    if (blockIdx.x < 1024) {
        float v = ctx[gid];
        uint32_t h, l; tf32split_(v, h, l);
        g_ctxh[gid] = __uint_as_float(h);
        g_ctxl[gid] = __uint_as_float(l);
    } else {
        int i = gid - 262144;           // 0..1048575
        int z = i >> 17, rem = i & 131071;
        int k = rem >> 10, n = rem & 1023;
        float v = 0.f;
        switch (z) {
            case 0: v = wch_W[k*1024 + n]; break;
            case 1: v = vch_W[k*1024 + n]; break;
            case 2: v = vep_W[k*4096 + n*4]; break;
            case 3: v = vep_W[k*4096 + n*4 + 2]; break;
            case 4: case 5: case 6: v = m_W[(z-4)*131072 + k*1024 + n]; break;
            default:
                if (n < 258) {
                    int s;
                    const float* p = sp_col(n, s, mod_W, wdl_W, wep_W, wnc_W, mb_W, wnd_W, wne_W);
                    v = p[k*s];
                }
                break;
        }
        uint32_t h, l; tf32split_(v, h, l);
        g_Bh[i] = __uint_as_float(h);
        g_Bl[i] = __uint_as_float(l);
    }
}

// smem layout (floats): A stride 36, B stride 136.
#define PA 36
#define PB 136
#define OFF_AHI 0
#define OFF_ALO (128*PA)
#define OFF_BHI (2*128*PA)
#define OFF_BLO (2*128*PA + 32*PB)
#define OFF_BIAS (2*128*PA + 2*32*PB)
#define SM_FLOATS (OFF_BIAS + 128)
#define SM_BYTES  (SM_FLOATS*4)

// =====================================================================
// Kernel 1: 8 GEMM slices, 3xTF32 mma.sync, pure-float4 loader.
// __launch_bounds__(256,2): 128-reg cap — NO spills (R13/R15 lesson).
// =====================================================================
__global__ __launch_bounds__(256, 2) void proj_tc(
    const float* __restrict__ wch_b, const float* __restrict__ vch_b,
    const float* __restrict__ vep_b, const float* __restrict__ m_Wb,
    const float* __restrict__ mod_b, const float* __restrict__ wdl_b,
    const float* __restrict__ wep_b, const float* __restrict__ wnc_b,
    const float* __restrict__ mb_b,  const float* __restrict__ wnd_b,
    const float* __restrict__ wne_b)
{
    const int bid = blockIdx.x;
    int bz, bx, by;
    if (bid < 896) { bz = bid >> 7; int rem = bid & 127; bx = rem >> 4; by = rem & 15; }
    else           { bz = 7; int rem = bid - 896; bx = rem >> 4; by = rem & 15; }

    const float* bias = nullptr; float* outp;
    int nstride = 1, noff = 0, ld_out = 1024, small = 0;
    switch (bz) {
        case 0: bias = wch_b; outp = g_wch; break;
        case 1: bias = vch_b; outp = g_vch; break;
        case 2: bias = vep_b; outp = g_vep0; nstride = 4; noff = 0; break;
        case 3: bias = vep_b; outp = g_vep2; nstride = 4; noff = 2; break;
        case 7: small = 1; outp = g_small; ld_out = 264; break;
        default: bias = m_Wb + (bz-4)*1024; outp = g_Wk + (bz-4)*NB*1024; break;
    }

    const int n0 = bx * 128;
    const int m0 = by * 128;

    extern __shared__ __align__(16) float smem[];
    float* AhF = smem + OFF_AHI;
    float* AlF = smem + OFF_ALO;
    float* BhF = smem + OFF_BHI;
    float* BlF = smem + OFF_BLO;
    float* bias_s = smem + OFF_BIAS;
    const uint32_t* Ah = reinterpret_cast<const uint32_t*>(AhF);
    const uint32_t* Al = reinterpret_cast<const uint32_t*>(AlF);
    const uint32_t* Bh = reinterpret_cast<const uint32_t*>(BhF);
    const uint32_t* Bl = reinterpret_cast<const uint32_t*>(BlF);

    const int tid  = threadIdx.x;
    const int wid  = tid >> 5, lane = tid & 31;
    const int g    = lane >> 2, tq = lane & 3;
    const int wm   = wid >> 1, wn = wid & 1;

    if (tid < 128) {
        float bv;
        if (small) bv = (n0 + tid < 258) ? sp_bias(n0+tid, mod_b, wdl_b, wep_b, wnc_b, mb_b, wnd_b, wne_b) : 0.f;
        else       bv = bias[(n0+tid)*nstride + noff];
        bias_s[tid] = bv;
    }

    const float* gBh = g_Bh + (size_t)bz*131072;
    const float* gBl = g_Bl + (size_t)bz*131072;

    float c[2][8][4];
    #pragma unroll
    for (int mi = 0; mi < 2; mi++)
        #pragma unroll
        for (int ni = 0; ni < 8; ni++)
            #pragma unroll
            for (int q = 0; q < 4; q++) c[mi][ni][q] = 0.f;

    for (int chunk = 0; chunk < 4; chunk++) {
        const int kc = chunk*32;
        if (chunk) __syncthreads();

        // A tile: 128 m x 32 k, float4 copies of pre-split ctx
        #pragma unroll
        for (int it = 0; it < 4; it++) {
            int idx = tid + it*256;            // 0..1023
            int m = idx >> 3, q4 = (idx & 7)*4;
            *(float4*)&AhF[m*PA + q4] = *(const float4*)&g_ctxh[(m0+m)*NC + kc + q4];
            *(float4*)&AlF[m*PA + q4] = *(const float4*)&g_ctxl[(m0+m)*NC + kc + q4];
        }
        // B tile: 32 k x 128 n
        #pragma unroll
        for (int it = 0; it < 4; it++) {
            int idx = tid + it*256;
            int k = idx >> 5, q4 = (idx & 31)*4;
            *(float4*)&BhF[k*PB + q4] = *(const float4*)&gBh[(kc+k)*1024 + n0 + q4];
            *(float4*)&BlF[k*PB + q4] = *(const float4*)&gBl[(kc+k)*1024 + n0 + q4];
        }
        __syncthreads();

        #pragma unroll
        for (int term = 0; term < 3; term++) {
            const uint32_t* As = (term == 2) ? Al : Ah;
            const uint32_t* Bs = (term == 1) ? Bl : Bh;
            #pragma unroll
            for (int kb = 0; kb < 32; kb += 8) {
                uint32_t a[2][4];
                #pragma unroll
                for (int mi = 0; mi < 2; mi++) {
                    int r0 = wm*32 + mi*16 + g;
                    a[mi][0] = As[(r0    )*PA + kb + tq];
                    a[mi][1] = As[(r0 + 8)*PA + kb + tq];
                    a[mi][2] = As[(r0    )*PA + kb + tq + 4];
                    a[mi][3] = As[(r0 + 8)*PA + kb + tq + 4];
                }
                #pragma unroll
                for (int ni = 0; ni < 8; ni++) {
                    int nb = wn*64 + ni*8 + g;
                    uint32_t b0 = Bs[(kb + tq    )*PB + nb];
                    uint32_t b1 = Bs[(kb + tq + 4)*PB + nb];
                    mma_tf32_(c[0][ni], a[0], b0, b1);
                    mma_tf32_(c[1][ni], a[1], b0, b1);
                }
            }
        }
    }
    __syncthreads();

    // ---- epilogue: stage warp tile 32x65, coalesced out ----
    float* stage = smem + wid*(32*65);
    #pragma unroll
    for (int mi = 0; mi < 2; mi++)
        #pragma unroll
        for (int ni = 0; ni < 8; ni++) {
            int r0 = mi*16 + g;
            int cc = ni*8 + 2*tq;
            stage[(r0    )*65 + cc    ] = c[mi][ni][0];
            stage[(r0    )*65 + cc + 1] = c[mi][ni][1];
            stage[(r0 + 8)*65 + cc    ] = c[mi][ni][2];
            stage[(r0 + 8)*65 + cc + 1] = c[mi][ni][3];
        }
    __syncwarp();
    const int ncol = wn*64;
    const int cg0 = n0 + ncol + lane;
    const int cg1 = cg0 + 32;
    #pragma unroll 4
    for (int r = 0; r < 32; r++) {
        int m = m0 + wm*32 + r;
        float v0 = stage[r*65 + lane]      + bias_s[ncol + lane];
        float v1 = stage[r*65 + 32 + lane] + bias_s[ncol + 32 + lane];
        if (!small || cg0 < 258) outp[(size_t)m*ld_out + cg0] = v0;
        if (!small || cg1 < 258) outp[(size_t)m*ld_out + cg1] = v1;
    }
}

// =====================================================================
// Kernel 2: per-batch fused kernel (unchanged from R14, 139.4us).
// =====================================================================
__global__ __launch_bounds__(256, 4) void scan_kernel(
    const float* __restrict__ form, float* __restrict__ out)
{
    const int b    = blockIdx.x;
    const int tid  = threadIdx.x;
    const int lane = tid & 31, wid = tid >> 5;

    __shared__ __align__(16) float form_t[32][68];
    __shared__ __align__(16) float big[3072];
    __shared__ float match_s[32][16];
    __shared__ float cw_s[96*32];
    __shared__ float segp_s[256];
    __shared__ __align__(16) float sym_s[32][64];
    __shared__ float sm_s[264];
    __shared__ float wnc_s[64];
    __shared__ float mod0_s[16], wdl_s[16], wep0_s[16], wep2_s[16];
    __shared__ float g_s[96], posn_s[96];
    __shared__ float scal2[2];

    for (int i = tid; i < 2048; i += 256) form_t[i & 31][i >> 5] = form[b*2048 + i];
    for (int j = tid; j < 258; j += 256) sm_s[j] = g_small[b*264 + j];
    for (int i = tid; i < 3072; i += 256)
        big[i] = g_Wk[(i >> 10)*(NB*1024) + b*1024 + (i & 1023)];
    __syncthreads();

    if (tid < 16) {
        float m[6], mx = -1e30f;
        #pragma unroll
        for (int ch = 0; ch < 6; ch++) { m[ch] = sm_s[tid*6+ch]; mx = fmaxf(mx, m[ch]); }
        float s = 0.f;
        #pragma unroll
        for (int ch = 0; ch < 6; ch++) { m[ch] = __expf(m[ch]-mx); s += m[ch]; }
        float inv = 1.f/s;
        mod0_s[tid] = m[0]*inv;
        wdl_s[tid]  = m[1]*inv*sm_s[96+tid];
        wep0_s[tid] = m[2]*inv*sm_s[112+tid];
        wep2_s[tid] = m[4]*inv*sm_s[128+tid];
    } else if (tid >= 64 && tid < 128) {
        wnc_s[tid-64] = __expf(sm_s[144 + tid-64]);
    } else if (tid == 128) scal2[0] = __expf(sm_s[256]);
    else if (tid == 129)   scal2[1] = __expf(sm_s[257]);

    {
        const int p0 = wid, p1 = wid + 8, r = lane;
        float prod0 = 1.f, prod1 = 1.f;
        #pragma unroll
        for (int k = 0; k < 3; k++) {
            float sa = sm_s[208 + k*16 + p0];
            float sb = sm_s[208 + k*16 + p1];
            int rr = r + k - 1;
            if (rr >= 0 && rr < 32) {
                const float* w0p = &big[k*1024 + p0*64];
                const float* w1p = &big[k*1024 + p1*64];
                float sa2 = 0.f, sb2 = 0.f;
                #pragma unroll 8
                for (int f = 0; f < 64; f += 8) {
                    float4 fv = *(const float4*)&form_t[rr][f];
                    float4 w0 = *(const float4*)&w0p[f];
                    float4 w1 = *(const float4*)&w1p[f];
                    sa  += w0.x*fv.x + w0.y*fv.y + w0.z*fv.z + w0.w*fv.w;
                    sb  += w1.x*fv.x + w1.y*fv.y + w1.z*fv.z + w1.w*fv.w;
                    float4 fv2 = *(const float4*)&form_t[rr][f+4];
                    float4 w02 = *(const float4*)&w0p[f+4];
                    float4 w12 = *(const float4*)&w1p[f+4];
                    sa2 += w02.x*fv2.x + w02.y*fv2.y + w02.z*fv2.z + w02.w*fv2.w;
                    sb2 += w12.x*fv2.x + w12.y*fv2.y + w12.z*fv2.z + w12.w*fv2.w;
                }
                sa += sa2; sb += sb2;
            }
            prod0 *= sigmoidf_(sa);
            prod1 *= sigmoidf_(sb);
        }
        match_s[r][p0] = prod0;
        match_s[r][p1] = prod1;
    }
    __syncthreads();

    {
        const float* pwch = g_wch + b*1024;
        const float* pvch = g_vch + b*1024;
        for (int i = tid; i < 1024; i += 256) {
            float u1 = mod0_s[i >> 6]*pwch[i];
            big[i]        = u1;
            big[1024 + i] = fmaxf(u1, 0.f)*pvch[i];
        }
    }
    if (tid < 96) {
        int i = tid/3, ph = tid - 3*i;
        const float* wv = (ph == 0) ? wep0_s : (ph == 1 ? wdl_s : wep2_s);
        float s = 0.f;
        #pragma unroll
        for (int p = 0; p < 16; p++) s += match_s[i][p]*wv[p];
        g_s[tid] = (ph == 1) ? (1.f - sigmoidf_(s - scal2[0]))
                             : sigmoidf_(s - scal2[1]);
    }
    __syncthreads();

    if (wid == 0) {
        float a0 = g_s[lane*3+0], a1 = g_s[lane*3+1], a2 = g_s[lane*3+2];
        float loc = a0 + a1 + a2;
        float sc = loc;
        #pragma unroll
        for (int off = 1; off < 32; off <<= 1) {
            float v = __shfl_up_sync(0xffffffffu, sc, off);
            if (lane >= off) sc += v;
        }
        float excl = sc - loc;
        posn_s[lane*3+0] = excl;
        posn_s[lane*3+1] = excl + a0;
        posn_s[lane*3+2] = excl + a0 + a1;
    }
    __syncthreads();

    #pragma unroll 4
    for (int k2 = 0; k2 < 12; k2++) {
        int st = wid*12 + k2;
        float pp = posn_s[st];
        float d  = pp - (float)lane;
        float rstar = fminf(fmaxf(rintf(pp), 0.f), 31.f);
        float dm = pp - rstar;
        float mx = -2.f*dm*dm;
        float e  = __expf(-2.f*d*d - mx);
        float ssum = e;
        #pragma unroll
        for (int off = 16; off; off >>= 1) ssum += __shfl_xor_sync(0xffffffffu, ssum, off);
        cw_s[st*32 + lane] = g_s[st]*e/ssum;
    }
    __syncthreads();

    {
        int st0 = wid*12;
        float run = 1.f;
        #pragma unroll
        for (int k2 = 11; k2 >= 0; k2--) {
            float cc = cw_s[(st0+k2)*32 + lane];
            cw_s[(st0+k2)*32 + lane] = cc*run;
            run *= (1.f - cc);
        }
        segp_s[wid*32 + lane] = run;
    }
    __syncthreads();
    {
        float mult = 1.f;
        #pragma unroll
        for (int w2 = 7; w2 >= 1; w2--) {
            float sp = segp_s[w2*32 + lane];
            if (w2 > wid) mult *= sp;
        }
        if (mult != 1.f) {
            int st0 = wid*12;
            #pragma unroll
            for (int k2 = 0; k2 < 12; k2++)
                cw_s[(st0+k2)*32 + lane] *= mult;
        }
    }
    __syncthreads();

    {
        int f4 = tid & 15, ii = tid >> 4;
        int f = f4*4;
        for (int rep = 0; rep < 2; rep++) {
            int i = ii + rep*16;
            float4 s1 = {0,0,0,0}, s2 = {0,0,0,0};
            #pragma unroll 8
            for (int p = 0; p < 16; p++) {
                float m = match_s[i][p];
                float4 u1 = *(const float4*)&big[p*64 + f];
                float4 u2 = *(const float4*)&big[1024 + p*64 + f];
                s1.x += m*u1.x; s1.y += m*u1.y; s1.z += m*u1.z; s1.w += m*u1.w;
                s2.x += m*u2.x; s2.y += m*u2.y; s2.z += m*u2.z; s2.w += m*u2.w;
            }
            float4 sy = *(const float4*)&form_t[i][f];
            float4 v;
            v.x = sy.x + sigmoidf_(s1.x - wnc_s[f  ])*(s2.x - sy.x);
            v.y = sy.y + sigmoidf_(s1.y - wnc_s[f+1])*(s2.y - sy.y);
            v.z = sy.z + sigmoidf_(s1.z - wnc_s[f+2])*(s2.z - sy.z);
            v.w = sy.w + sigmoidf_(s1.w - wnc_s[f+3])*(s2.w - sy.w);
            *(float4*)&sym_s[i][f] = v;
        }
    }
    __syncthreads();

    float2* Mpair = reinterpret_cast<float2*>(&form_t[0][0]);
    {
        const float* pv0 = g_vep0 + b*1024;
        const float* pv2 = g_vep2 + b*1024;
        for (int i = tid; i < 1024; i += 256) {
            int p = i >> 6;
            big[i]        = fmaxf(wep0_s[p], 0.f)*pv0[i];
            big[1024 + i] = fmaxf(wep2_s[p], 0.f)*pv2[i];
        }
    }
    {
        int p0 = wid, p1 = wid + 8;
        float a00 = 0.f, a01 = 0.f, a20 = 0.f, a21 = 0.f;
        #pragma unroll 8
        for (int i = 0; i < 32; i++) {
            float w0 = cw_s[(3*i  )*32 + lane];
            float w2 = cw_s[(3*i+2)*32 + lane];
            float m0 = match_s[i][p0], m1v = match_s[i][p1];
            a00 += m0*w0;  a01 += m1v*w0;
            a20 += m0*w2;  a21 += m1v*w2;
        }
        Mpair[p0*32 + lane] = make_float2(a00, a20);
        Mpair[p1*32 + lane] = make_float2(a01, a21);
    }
    __syncthreads();

    const int fb = wid*8;
    {
        float o0=0.f,o1=0.f,o2=0.f,o3=0.f,o4=0.f,o5=0.f,o6=0.f,o7=0.f;
        #pragma unroll 8
        for (int p = 0; p < 16; p++) {
            float2 ap = Mpair[p*32 + lane];
            float a0 = ap.x, a2 = ap.y;
            float4 v00 = *(const float4*)&big[p*64 + fb];
            float4 v01 = *(const float4*)&big[p*64 + fb + 4];
            float4 v20 = *(const float4*)&big[1024 + p*64 + fb];
            float4 v21 = *(const float4*)&big[1024 + p*64 + fb + 4];
            o0 += a0*v00.x + a2*v20.x;  o1 += a0*v00.y + a2*v20.y;
            o2 += a0*v00.z + a2*v20.z;  o3 += a0*v00.w + a2*v20.w;
            o4 += a0*v01.x + a2*v21.x;  o5 += a0*v01.y + a2*v21.y;
            o6 += a0*v01.z + a2*v21.z;  o7 += a0*v01.w + a2*v21.w;
        }
        #pragma unroll 8
        for (int i = 0; i < 32; i++) {
            float w1 = cw_s[(3*i+1)*32 + lane];
            float4 s0 = *(const float4*)&sym_s[i][fb];
            float4 s1v = *(const float4*)&sym_s[i][fb + 4];
            o0 += w1*s0.x;  o1 += w1*s0.y;  o2 += w1*s0.z;  o3 += w1*s0.w;
            o4 += w1*s1v.x; o5 += w1*s1v.y; o6 += w1*s1v.z; o7 += w1*s1v.w;
        }
        out[b*2048 + (fb  )*32 + lane] = o0;
        out[b*2048 + (fb+1)*32 + lane] = o1;
        out[b*2048 + (fb+2)*32 + lane] = o2;
        out[b*2048 + (fb+3)*32 + lane] = o3;
        out[b*2048 + (fb+4)*32 + lane] = o4;
        out[b*2048 + (fb+5)*32 + lane] = o5;
        out[b*2048 + (fb+6)*32 + lane] = o6;
        out[b*2048 + (fb+7)*32 + lane] = o7;
    }
}

// =====================================================================
extern "C" void kernel_launch(void* const* d_in, const int* in_sizes, int n_in,
                              void* d_out, int out_size)
{
    (void)in_sizes; (void)n_in; (void)out_size;
    const float* form  = (const float*)d_in[0];
    const float* ctx   = (const float*)d_in[1];
    const float* mod_W = (const float*)d_in[2];
    const float* mod_b = (const float*)d_in[3];
    const float* wch_W = (const float*)d_in[4];
    const float* wch_b = (const float*)d_in[5];
    const float* wdl_W = (const float*)d_in[6];
    const float* wdl_b = (const float*)d_in[7];
    const float* wep_W = (const float*)d_in[8];
    const float* wep_b = (const float*)d_in[9];
    const float* vch_W = (const float*)d_in[10];
    const float* vch_b = (const float*)d_in[11];
    const float* vep_W = (const float*)d_in[12];
    const float* vep_b = (const float*)d_in[13];
    const float* wnc_W = (const float*)d_in[14];
    const float* wnc_b = (const float*)d_in[15];
    const float* wnd_W = (const float*)d_in[16];
    const float* wnd_b = (const float*)d_in[17];
    const float* wne_W = (const float*)d_in[18];
    const float* wne_b = (const float*)d_in[19];
    const float* m_W   = (const float*)d_in[20];
    const float* m_Wb  = (const float*)d_in[21];
    const float* mb_W  = (const float*)d_in[22];
    const float* mb_b  = (const float*)d_in[23];

    static int smem_set = 0;
    if (!smem_set) {
        cudaFuncSetAttribute(proj_tc, cudaFuncAttributeMaxDynamicSharedMemorySize, SM_BYTES);
        smem_set = 1;
    }

    prep_split<<<5120, 256>>>(ctx, wch_W, vch_W, vep_W, m_W,
                              mod_W, wdl_W, wep_W, wnc_W, mb_W, wnd_W, wne_W);

    proj_tc<<<944, 256, SM_BYTES>>>(wch_b, vch_b, vep_b, m_Wb,
                                    mod_b, wdl_b, wep_b, wnc_b, mb_b, wnd_b, wne_b);

    scan_kernel<<<NB, 256>>>(form, (float*)d_out);
}

// round 17
// speedup vs baseline: 1.5314x; 1.0285x over previous
#include <cuda_runtime.h>
#include <cstdint>

#define NB 2048
#define NF 64
#define NR 32
#define NP 16
#define NC 128

// ---------------- scratch ----------------
__device__ float g_wch [NB*1024];
__device__ float g_vch [NB*1024];
__device__ float g_vep0[NB*1024];
__device__ float g_vep2[NB*1024];
__device__ float g_Wk  [3*NB*1024];
__device__ float g_small[NB*264];
// pre-split tf32 hi/lo buffers
__device__ float g_ctxh[NB*NC];
__device__ float g_ctxl[NB*NC];
__device__ float g_Bh  [8*128*1024];
__device__ float g_Bl  [8*128*1024];

__device__ __forceinline__ float sigmoidf_(float x) { return 1.f/(1.f + __expf(-x)); }

// ---- 3xTF32 helpers (family-portable PTX, sm_80+) ----
__device__ __forceinline__ void tf32split_(float x, uint32_t& hi, uint32_t& lo) {
    uint32_t h;
    asm("cvt.rna.tf32.f32 %0, %1;" : "=r"(h) : "f"(x));
    float r = x - __uint_as_float(h);
    uint32_t l;
    asm("cvt.rna.tf32.f32 %0, %1;" : "=r"(l) : "f"(r));
    hi = h; lo = l;
}
__device__ __forceinline__ void mma_tf32_(float* c, const uint32_t* a, uint32_t b0, uint32_t b1) {
    asm volatile(
        "mma.sync.aligned.m16n8k8.row.col.f32.tf32.tf32.f32 "
        "{%0,%1,%2,%3}, {%4,%5,%6,%7}, {%8,%9}, {%0,%1,%2,%3};"
        : "+f"(c[0]), "+f"(c[1]), "+f"(c[2]), "+f"(c[3])
        : "r"(a[0]), "r"(a[1]), "r"(a[2]), "r"(a[3]), "r"(b0), "r"(b1));
}
__device__ __forceinline__ uint32_t smem_u32_(const void* p) {
    uint32_t a;
    asm("{ .reg .u64 t; cvta.to.shared.u64 t, %1; cvt.u32.u64 %0, t; }" : "=r"(a) : "l"(p));
    return a;
}
#define CP_ASYNC16(dst_u32, src) \
    asm volatile("cp.async.cg.shared.global [%0], [%1], 16;" :: "r"(dst_u32), "l"(src))
#define CP_COMMIT()  asm volatile("cp.async.commit_group;" ::: "memory")
#define CP_WAIT0()   asm volatile("cp.async.wait_group 0;" ::: "memory")

// ---- small-projection column map (258 cols) ----
__device__ __forceinline__ const float* sp_col(int n, int& stride,
    const float* mod_W, const float* wdl_W, const float* wep_W,
    const float* wnc_W, const float* mb_W, const float* wnd_W, const float* wne_W)
{
    if (n < 96)  { stride = 96; return mod_W + n; }
    if (n < 112) { stride = 16; return wdl_W + (n-96); }
    if (n < 128) { stride = 64; return wep_W + (n-112)*4; }
    if (n < 144) { stride = 64; return wep_W + (n-128)*4 + 2; }
    if (n < 208) { stride = 64; return wnc_W + (n-144); }
    if (n < 256) { int idx = n-208; stride = 16; return mb_W + (idx>>4)*2048 + (idx&15); }
    if (n == 256){ stride = 1; return wnd_W; }
    stride = 1; return wne_W;
}
__device__ __forceinline__ float sp_bias(int n,
    const float* mod_b, const float* wdl_b, const float* wep_b,
    const float* wnc_b, const float* mb_b, const float* wnd_b, const float* wne_b)
{
    if (n < 96)  return mod_b[n];
    if (n < 112) return wdl_b[n-96];
    if (n < 128) return wep_b[(n-112)*4];
    if (n < 144) return wep_b[(n-128)*4 + 2];
    if (n < 208) return wnc_b[n-144];
    if (n < 256) return mb_b[n-208];
    if (n == 256) return wnd_b[0];
    return wne_b[0];
}

// =====================================================================
// Kernel 0: pre-split ctx and all B slices into tf32 hi/lo buffers.
// =====================================================================
__global__ __launch_bounds__(256) void prep_split(
    const float* __restrict__ ctx,
    const float* __restrict__ wch_W, const float* __restrict__ vch_W,
    const float* __restrict__ vep_W, const float* __restrict__ m_W,
    const float* __restrict__ mod_W, const float* __restrict__ wdl_W,
    const float* __restrict__ wep_W, const float* __restrict__ wnc_W,
    const float* __restrict__ mb_W,  const float* __restrict__ wnd_W,
    const float* __restrict__ wne_W)
{
    int gid = blockIdx.x*256 + threadIdx.x;
    if (blockIdx.x < 1024) {
        float v = ctx[gid];
        uint32_t h, l; tf32split_(v, h, l);
        g_ctxh[gid] = __uint_as_float(h);
        g_ctxl[gid] = __uint_as_float(l);
    } else {
        int i = gid - 262144;           // 0..1048575
        int z = i >> 17, rem = i & 131071;
        int k = rem >> 10, n = rem & 1023;
        float v = 0.f;
        switch (z) {
            case 0: v = wch_W[k*1024 + n]; break;
            case 1: v = vch_W[k*1024 + n]; break;
            case 2: v = vep_W[k*4096 + n*4]; break;
            case 3: v = vep_W[k*4096 + n*4 + 2]; break;
            case 4: case 5: case 6: v = m_W[(z-4)*131072 + k*1024 + n]; break;
            default:
                if (n < 258) {
                    int s;
                    const float* p = sp_col(n, s, mod_W, wdl_W, wep_W, wnc_W, mb_W, wnd_W, wne_W);
                    v = p[k*s];
                }
                break;
        }
        uint32_t h, l; tf32split_(v, h, l);
        g_Bh[i] = __uint_as_float(h);
        g_Bl[i] = __uint_as_float(l);
    }
}

// smem layout (floats): A stride 36, B stride 136; two pipeline stages.
#define PA 36
#define PB 136
#define OFF_AHI 0
#define OFF_ALO (128*PA)                  // 4608
#define OFF_BHI (2*128*PA)                // 9216
#define OFF_BLO (2*128*PA + 32*PB)        // 13568
#define STAGE_FLOATS (2*128*PA + 2*32*PB) // 17920
#define OFF_BIAS (2*STAGE_FLOATS)         // 35840
#define SM_FLOATS (OFF_BIAS + 128)        // 35968
#define SM_BYTES  (SM_FLOATS*4)           // 143872

// =====================================================================
// Kernel 1: 8 GEMM slices, 3xTF32 mma.sync, cp.async double-buffered.
// 1 CTA/SM (smem-bound), loads fully overlap MMA, zero reg pressure.
// =====================================================================
__global__ __launch_bounds__(256) void proj_tc(
    const float* __restrict__ wch_b, const float* __restrict__ vch_b,
    const float* __restrict__ vep_b, const float* __restrict__ m_Wb,
    const float* __restrict__ mod_b, const float* __restrict__ wdl_b,
    const float* __restrict__ wep_b, const float* __restrict__ wnc_b,
    const float* __restrict__ mb_b,  const float* __restrict__ wnd_b,
    const float* __restrict__ wne_b)
{
    const int bid = blockIdx.x;
    int bz, bx, by;
    if (bid < 896) { bz = bid >> 7; int rem = bid & 127; bx = rem >> 4; by = rem & 15; }
    else           { bz = 7; int rem = bid - 896; bx = rem >> 4; by = rem & 15; }

    const float* bias = nullptr; float* outp;
    int nstride = 1, noff = 0, ld_out = 1024, small = 0;
    switch (bz) {
        case 0: bias = wch_b; outp = g_wch; break;
        case 1: bias = vch_b; outp = g_vch; break;
        case 2: bias = vep_b; outp = g_vep0; nstride = 4; noff = 0; break;
        case 3: bias = vep_b; outp = g_vep2; nstride = 4; noff = 2; break;
        case 7: small = 1; outp = g_small; ld_out = 264; break;
        default: bias = m_Wb + (bz-4)*1024; outp = g_Wk + (bz-4)*NB*1024; break;
    }

    const int n0 = bx * 128;
    const int m0 = by * 128;

    extern __shared__ __align__(16) float smem[];
    float* bias_s = smem + OFF_BIAS;

    const int tid  = threadIdx.x;
    const int wid  = tid >> 5, lane = tid & 31;
    const int g    = lane >> 2, tq = lane & 3;
    const int wm   = wid >> 1, wn = wid & 1;

    if (tid < 128) {
        float bv;
        if (small) bv = (n0 + tid < 258) ? sp_bias(n0+tid, mod_b, wdl_b, wep_b, wnc_b, mb_b, wnd_b, wne_b) : 0.f;
        else       bv = bias[(n0+tid)*nstride + noff];
        bias_s[tid] = bv;
    }

    const float* gBh = g_Bh + (size_t)bz*131072;
    const float* gBl = g_Bl + (size_t)bz*131072;

    // per-thread loader geometry (fixed across chunks)
    const int mA = tid >> 1, qA = (tid & 1)*16;     // A: 128 rows x 32k -> 2 float4-pairs/thread? no:
    // A tile: 128 x 32 floats = 4096 = 1024 float4 (x2 hi/lo). 256 thr -> 4 float4 each per buffer.
    // Use idx = tid + it*256, it<4: m = idx>>3, q4 = (idx&7)*4.
    // B tile: 32 x 128 = 4096 = 1024 float4 (x2). same decomposition: k = idx>>5, q4=(idx&31)*4.
    (void)mA; (void)qA;

    const uint32_t smem_base_u32 = smem_u32_(smem);

    auto issue_chunk = [&](int chunk, int stage) {
        const int kc = chunk*32;
        const uint32_t sb = smem_base_u32 + stage*STAGE_FLOATS*4;
        #pragma unroll
        for (int it = 0; it < 4; it++) {
            int idx = tid + it*256;
            int m = idx >> 3, q4 = (idx & 7)*4;
            uint32_t dh = sb + (OFF_AHI + m*PA + q4)*4;
            uint32_t dl = sb + (OFF_ALO + m*PA + q4)*4;
            CP_ASYNC16(dh, &g_ctxh[(m0+m)*NC + kc + q4]);
            CP_ASYNC16(dl, &g_ctxl[(m0+m)*NC + kc + q4]);
        }
        #pragma unroll
        for (int it = 0; it < 4; it++) {
            int idx = tid + it*256;
            int k = idx >> 5, q4 = (idx & 31)*4;
            uint32_t dh = sb + (OFF_BHI + k*PB + q4)*4;
            uint32_t dl = sb + (OFF_BLO + k*PB + q4)*4;
            CP_ASYNC16(dh, &gBh[(kc+k)*1024 + n0 + q4]);
            CP_ASYNC16(dl, &gBl[(kc+k)*1024 + n0 + q4]);
        }
        CP_COMMIT();
    };

    float c[2][8][4];
    #pragma unroll
    for (int mi = 0; mi < 2; mi++)
        #pragma unroll
        for (int ni = 0; ni < 8; ni++)
            #pragma unroll
            for (int q = 0; q < 4; q++) c[mi][ni][q] = 0.f;

    issue_chunk(0, 0);

    for (int chunk = 0; chunk < 4; chunk++) {
        const int s = chunk & 1;
        CP_WAIT0();
        __syncthreads();           // all warps done with prior mma on stage s, data for chunk ready
        if (chunk < 3) issue_chunk(chunk+1, s^1);

        const float* st = smem + s*STAGE_FLOATS;
        const uint32_t* Ah = reinterpret_cast<const uint32_t*>(st + OFF_AHI);
        const uint32_t* Al = reinterpret_cast<const uint32_t*>(st + OFF_ALO);
        const uint32_t* Bh = reinterpret_cast<const uint32_t*>(st + OFF_BHI);
        const uint32_t* Bl = reinterpret_cast<const uint32_t*>(st + OFF_BLO);

        #pragma unroll
        for (int term = 0; term < 3; term++) {
            const uint32_t* As = (term == 2) ? Al : Ah;
            const uint32_t* Bs = (term == 1) ? Bl : Bh;
            #pragma unroll
            for (int kb = 0; kb < 32; kb += 8) {
                uint32_t a[2][4];
                #pragma unroll
                for (int mi = 0; mi < 2; mi++) {
                    int r0 = wm*32 + mi*16 + g;
                    a[mi][0] = As[(r0    )*PA + kb + tq];
                    a[mi][1] = As[(r0 + 8)*PA + kb + tq];
                    a[mi][2] = As[(r0    )*PA + kb + tq + 4];
                    a[mi][3] = As[(r0 + 8)*PA + kb + tq + 4];
                }
                #pragma unroll
                for (int ni = 0; ni < 8; ni++) {
                    int nb = wn*64 + ni*8 + g;
                    uint32_t b0 = Bs[(kb + tq    )*PB + nb];
                    uint32_t b1 = Bs[(kb + tq + 4)*PB + nb];
                    mma_tf32_(c[0][ni], a[0], b0, b1);
                    mma_tf32_(c[1][ni], a[1], b0, b1);
                }
            }
        }
    }
    __syncthreads();

    // ---- epilogue: stage warp tile 32x65, coalesced out ----
    float* stage = smem + wid*(32*65);
    #pragma unroll
    for (int mi = 0; mi < 2; mi++)
        #pragma unroll
        for (int ni = 0; ni < 8; ni++) {
            int r0 = mi*16 + g;
            int cc = ni*8 + 2*tq;
            stage[(r0    )*65 + cc    ] = c[mi][ni][0];
            stage[(r0    )*65 + cc + 1] = c[mi][ni][1];
            stage[(r0 + 8)*65 + cc    ] = c[mi][ni][2];
            stage[(r0 + 8)*65 + cc + 1] = c[mi][ni][3];
        }
    __syncwarp();
    const int ncol = wn*64;
    const int cg0 = n0 + ncol + lane;
    const int cg1 = cg0 + 32;
    #pragma unroll 4
    for (int r = 0; r < 32; r++) {
        int m = m0 + wm*32 + r;
        float v0 = stage[r*65 + lane]      + bias_s[ncol + lane];
        float v1 = stage[r*65 + 32 + lane] + bias_s[ncol + 32 + lane];
        if (!small || cg0 < 258) outp[(size_t)m*ld_out + cg0] = v0;
        if (!small || cg1 < 258) outp[(size_t)m*ld_out + cg1] = v1;
    }
}

// =====================================================================
// Kernel 2: per-batch fused kernel (unchanged from R16, 139.4us).
// =====================================================================
__global__ __launch_bounds__(256, 4) void scan_kernel(
    const float* __restrict__ form, float* __restrict__ out)
{
    const int b    = blockIdx.x;
    const int tid  = threadIdx.x;
    const int lane = tid & 31, wid = tid >> 5;

    __shared__ __align__(16) float form_t[32][68];
    __shared__ __align__(16) float big[3072];
    __shared__ float match_s[32][16];
    __shared__ float cw_s[96*32];
    __shared__ float segp_s[256];
    __shared__ __align__(16) float sym_s[32][64];
    __shared__ float sm_s[264];
    __shared__ float wnc_s[64];
    __shared__ float mod0_s[16], wdl_s[16], wep0_s[16], wep2_s[16];
    __shared__ float g_s[96], posn_s[96];
    __shared__ float scal2[2];

    for (int i = tid; i < 2048; i += 256) form_t[i & 31][i >> 5] = form[b*2048 + i];
    for (int j = tid; j < 258; j += 256) sm_s[j] = g_small[b*264 + j];
    for (int i = tid; i < 3072; i += 256)
        big[i] = g_Wk[(i >> 10)*(NB*1024) + b*1024 + (i & 1023)];
    __syncthreads();

    if (tid < 16) {
        float m[6], mx = -1e30f;
        #pragma unroll
        for (int ch = 0; ch < 6; ch++) { m[ch] = sm_s[tid*6+ch]; mx = fmaxf(mx, m[ch]); }
        float s = 0.f;
        #pragma unroll
        for (int ch = 0; ch < 6; ch++) { m[ch] = __expf(m[ch]-mx); s += m[ch]; }
        float inv = 1.f/s;
        mod0_s[tid] = m[0]*inv;
        wdl_s[tid]  = m[1]*inv*sm_s[96+tid];
        wep0_s[tid] = m[2]*inv*sm_s[112+tid];
        wep2_s[tid] = m[4]*inv*sm_s[128+tid];
    } else if (tid >= 64 && tid < 128) {
        wnc_s[tid-64] = __expf(sm_s[144 + tid-64]);
    } else if (tid == 128) scal2[0] = __expf(sm_s[256]);
    else if (tid == 129)   scal2[1] = __expf(sm_s[257]);

    {
        const int p0 = wid, p1 = wid + 8, r = lane;
        float prod0 = 1.f, prod1 = 1.f;
        #pragma unroll
        for (int k = 0; k < 3; k++) {
            float sa = sm_s[208 + k*16 + p0];
            float sb = sm_s[208 + k*16 + p1];
            int rr = r + k - 1;
            if (rr >= 0 && rr < 32) {
                const float* w0p = &big[k*1024 + p0*64];
                const float* w1p = &big[k*1024 + p1*64];
                float sa2 = 0.f, sb2 = 0.f;
                #pragma unroll 8
                for (int f = 0; f < 64; f += 8) {
                    float4 fv = *(const float4*)&form_t[rr][f];
                    float4 w0 = *(const float4*)&w0p[f];
                    float4 w1 = *(const float4*)&w1p[f];
                    sa  += w0.x*fv.x + w0.y*fv.y + w0.z*fv.z + w0.w*fv.w;
                    sb  += w1.x*fv.x + w1.y*fv.y + w1.z*fv.z + w1.w*fv.w;
                    float4 fv2 = *(const float4*)&form_t[rr][f+4];
                    float4 w02 = *(const float4*)&w0p[f+4];
                    float4 w12 = *(const float4*)&w1p[f+4];
                    sa2 += w02.x*fv2.x + w02.y*fv2.y + w02.z*fv2.z + w02.w*fv2.w;
                    sb2 += w12.x*fv2.x + w12.y*fv2.y + w12.z*fv2.z + w12.w*fv2.w;
                }
                sa += sa2; sb += sb2;
            }
            prod0 *= sigmoidf_(sa);
            prod1 *= sigmoidf_(sb);
        }
        match_s[r][p0] = prod0;
        match_s[r][p1] = prod1;
    }
    __syncthreads();

    {
        const float* pwch = g_wch + b*1024;
        const float* pvch = g_vch + b*1024;
        for (int i = tid; i < 1024; i += 256) {
            float u1 = mod0_s[i >> 6]*pwch[i];
            big[i]        = u1;
            big[1024 + i] = fmaxf(u1, 0.f)*pvch[i];
        }
    }
    if (tid < 96) {
        int i = tid/3, ph = tid - 3*i;
        const float* wv = (ph == 0) ? wep0_s : (ph == 1 ? wdl_s : wep2_s);
        float s = 0.f;
        #pragma unroll
        for (int p = 0; p < 16; p++) s += match_s[i][p]*wv[p];
        g_s[tid] = (ph == 1) ? (1.f - sigmoidf_(s - scal2[0]))
                             : sigmoidf_(s - scal2[1]);
    }
    __syncthreads();

    if (wid == 0) {
        float a0 = g_s[lane*3+0], a1 = g_s[lane*3+1], a2 = g_s[lane*3+2];
        float loc = a0 + a1 + a2;
        float sc = loc;
        #pragma unroll
        for (int off = 1; off < 32; off <<= 1) {
            float v = __shfl_up_sync(0xffffffffu, sc, off);
            if (lane >= off) sc += v;
        }
        float excl = sc - loc;
        posn_s[lane*3+0] = excl;
        posn_s[lane*3+1] = excl + a0;
        posn_s[lane*3+2] = excl + a0 + a1;
    }
    __syncthreads();

    #pragma unroll 4
    for (int k2 = 0; k2 < 12; k2++) {
        int st = wid*12 + k2;
        float pp = posn_s[st];
        float d  = pp - (float)lane;
        float rstar = fminf(fmaxf(rintf(pp), 0.f), 31.f);
        float dm = pp - rstar;
        float mx = -2.f*dm*dm;
        float e  = __expf(-2.f*d*d - mx);
        float ssum = e;
        #pragma unroll
        for (int off = 16; off; off >>= 1) ssum += __shfl_xor_sync(0xffffffffu, ssum, off);
        cw_s[st*32 + lane] = g_s[st]*e/ssum;
    }
    __syncthreads();

    {
        int st0 = wid*12;
        float run = 1.f;
        #pragma unroll
        for (int k2 = 11; k2 >= 0; k2--) {
            float cc = cw_s[(st0+k2)*32 + lane];
            cw_s[(st0+k2)*32 + lane] = cc*run;
            run *= (1.f - cc);
        }
        segp_s[wid*32 + lane] = run;
    }
    __syncthreads();
    {
        float mult = 1.f;
        #pragma unroll
        for (int w2 = 7; w2 >= 1; w2--) {
            float sp = segp_s[w2*32 + lane];
            if (w2 > wid) mult *= sp;
        }
        if (mult != 1.f) {
            int st0 = wid*12;
            #pragma unroll
            for (int k2 = 0; k2 < 12; k2++)
                cw_s[(st0+k2)*32 + lane] *= mult;
        }
    }
    __syncthreads();

    {
        int f4 = tid & 15, ii = tid >> 4;
        int f = f4*4;
        for (int rep = 0; rep < 2; rep++) {
            int i = ii + rep*16;
            float4 s1 = {0,0,0,0}, s2 = {0,0,0,0};
            #pragma unroll 8
            for (int p = 0; p < 16; p++) {
                float m = match_s[i][p];
                float4 u1 = *(const float4*)&big[p*64 + f];
                float4 u2 = *(const float4*)&big[1024 + p*64 + f];
                s1.x += m*u1.x; s1.y += m*u1.y; s1.z += m*u1.z; s1.w += m*u1.w;
                s2.x += m*u2.x; s2.y += m*u2.y; s2.z += m*u2.z; s2.w += m*u2.w;
            }
            float4 sy = *(const float4*)&form_t[i][f];
            float4 v;
            v.x = sy.x + sigmoidf_(s1.x - wnc_s[f  ])*(s2.x - sy.x);
            v.y = sy.y + sigmoidf_(s1.y - wnc_s[f+1])*(s2.y - sy.y);
            v.z = sy.z + sigmoidf_(s1.z - wnc_s[f+2])*(s2.z - sy.z);
            v.w = sy.w + sigmoidf_(s1.w - wnc_s[f+3])*(s2.w - sy.w);
            *(float4*)&sym_s[i][f] = v;
        }
    }
    __syncthreads();

    float2* Mpair = reinterpret_cast<float2*>(&form_t[0][0]);
    {
        const float* pv0 = g_vep0 + b*1024;
        const float* pv2 = g_vep2 + b*1024;
        for (int i = tid; i < 1024; i += 256) {
            int p = i >> 6;
            big[i]        = fmaxf(wep0_s[p], 0.f)*pv0[i];
            big[1024 + i] = fmaxf(wep2_s[p], 0.f)*pv2[i];
        }
    }
    {
        int p0 = wid, p1 = wid + 8;
        float a00 = 0.f, a01 = 0.f, a20 = 0.f, a21 = 0.f;
        #pragma unroll 8
        for (int i = 0; i < 32; i++) {
            float w0 = cw_s[(3*i  )*32 + lane];
            float w2 = cw_s[(3*i+2)*32 + lane];
            float m0 = match_s[i][p0], m1v = match_s[i][p1];
            a00 += m0*w0;  a01 += m1v*w0;
            a20 += m0*w2;  a21 += m1v*w2;
        }
        Mpair[p0*32 + lane] = make_float2(a00, a20);
        Mpair[p1*32 + lane] = make_float2(a01, a21);
    }
    __syncthreads();

    const int fb = wid*8;
    {
        float o0=0.f,o1=0.f,o2=0.f,o3=0.f,o4=0.f,o5=0.f,o6=0.f,o7=0.f;
        #pragma unroll 8
        for (int p = 0; p < 16; p++) {
            float2 ap = Mpair[p*32 + lane];
            float a0 = ap.x, a2 = ap.y;
            float4 v00 = *(const float4*)&big[p*64 + fb];
            float4 v01 = *(const float4*)&big[p*64 + fb + 4];
            float4 v20 = *(const float4*)&big[1024 + p*64 + fb];
            float4 v21 = *(const float4*)&big[1024 + p*64 + fb + 4];
            o0 += a0*v00.x + a2*v20.x;  o1 += a0*v00.y + a2*v20.y;
            o2 += a0*v00.z + a2*v20.z;  o3 += a0*v00.w + a2*v20.w;
            o4 += a0*v01.x + a2*v21.x;  o5 += a0*v01.y + a2*v21.y;
            o6 += a0*v01.z + a2*v21.z;  o7 += a0*v01.w + a2*v21.w;
        }
        #pragma unroll 8
        for (int i = 0; i < 32; i++) {
            float w1 = cw_s[(3*i+1)*32 + lane];
            float4 s0 = *(const float4*)&sym_s[i][fb];
            float4 s1v = *(const float4*)&sym_s[i][fb + 4];
            o0 += w1*s0.x;  o1 += w1*s0.y;  o2 += w1*s0.z;  o3 += w1*s0.w;
            o4 += w1*s1v.x; o5 += w1*s1v.y; o6 += w1*s1v.z; o7 += w1*s1v.w;
        }
        out[b*2048 + (fb  )*32 + lane] = o0;
        out[b*2048 + (fb+1)*32 + lane] = o1;
        out[b*2048 + (fb+2)*32 + lane] = o2;
        out[b*2048 + (fb+3)*32 + lane] = o3;
        out[b*2048 + (fb+4)*32 + lane] = o4;
        out[b*2048 + (fb+5)*32 + lane] = o5;
        out[b*2048 + (fb+6)*32 + lane] = o6;
        out[b*2048 + (fb+7)*32 + lane] = o7;
    }
}

// =====================================================================
extern "C" void kernel_launch(void* const* d_in, const int* in_sizes, int n_in,
                              void* d_out, int out_size)
{
    (void)in_sizes; (void)n_in; (void)out_size;
    const float* form  = (const float*)d_in[0];
    const float* ctx   = (const float*)d_in[1];
    const float* mod_W = (const float*)d_in[2];
    const float* mod_b = (const float*)d_in[3];
    const float* wch_W = (const float*)d_in[4];
    const float* wch_b = (const float*)d_in[5];
    const float* wdl_W = (const float*)d_in[6];
    const float* wdl_b = (const float*)d_in[7];
    const float* wep_W = (const float*)d_in[8];
    const float* wep_b = (const float*)d_in[9];
    const float* vch_W = (const float*)d_in[10];
    const float* vch_b = (const float*)d_in[11];
    const float* vep_W = (const float*)d_in[12];
    const float* vep_b = (const float*)d_in[13];
    const float* wnc_W = (const float*)d_in[14];
    const float* wnc_b = (const float*)d_in[15];
    const float* wnd_W = (const float*)d_in[16];
    const float* wnd_b = (const float*)d_in[17];
    const float* wne_W = (const float*)d_in[18];
    const float* wne_b = (const float*)d_in[19];
    const float* m_W   = (const float*)d_in[20];
    const float* m_Wb  = (const float*)d_in[21];
    const float* mb_W  = (const float*)d_in[22];
    const float* mb_b  = (const float*)d_in[23];

    static int smem_set = 0;
    if (!smem_set) {
        cudaFuncSetAttribute(proj_tc, cudaFuncAttributeMaxDynamicSharedMemorySize, SM_BYTES);
        smem_set = 1;
    }

    prep_split<<<5120, 256>>>(ctx, wch_W, vch_W, vep_W, m_W,
                              mod_W, wdl_W, wep_W, wnc_W, mb_W, wnd_W, wne_W);

    proj_tc<<<944, 256, SM_BYTES>>>(wch_b, vch_b, vep_b, m_Wb,
                                    mod_b, wdl_b, wep_b, wnc_b, mb_b, wnd_b, wne_b);

    scan_kernel<<<NB, 256>>>(form, (float*)d_out);
}